// round 1
// baseline (speedup 1.0000x reference)
#include <cuda_runtime.h>
#include <math.h>
#include <stdint.h>

#define B_  16
#define L_  1024
#define E_  128
#define DI  256
#define DS  48
#define KC  4
#define DTR 8
#define XD  104           // DTR + 2*DS
#define BL  (B_*L_)

// ---------------- scratch (single static device array; no allocation) -------
#define N_CONV   ((size_t)B_*E_*L_)       // 2,097,152
#define N_HT     ((size_t)BL*E_)          // 2,097,152
#define N_XZ     ((size_t)BL*2*DI)        // 8,388,608
#define N_XC     ((size_t)BL*DI)          // 4,194,304
#define N_XD     ((size_t)BL*XD)          // 1,703,936

#define OFF_H0   ((size_t)0)
#define OFF_H1   (OFF_H0 + N_CONV)
#define OFF_GEL  (OFF_H1 + N_CONV)
#define OFF_HT   (OFF_GEL + N_CONV)
#define OFF_U    (OFF_HT + N_HT)
#define OFF_XZ   (OFF_U + N_HT)
#define OFF_XC0  (OFF_XZ + N_XZ)
#define OFF_XC1  (OFF_XC0 + N_XC)
#define OFF_XD0  (OFF_XC1 + N_XC)
#define OFF_XD1  (OFF_XD0 + N_XD)
#define OFF_DL0  (OFF_XD1 + N_XD)
#define OFF_DL1  (OFF_DL0 + N_XC)
#define OFF_Y0   (OFF_DL1 + N_XC)
#define OFF_Y1   (OFF_Y0 + N_XC)
#define OFF_YG   (OFF_Y1 + N_XC)
#define SCRATCH_TOTAL (OFF_YG + N_XC)

static __device__ float g_scratch[SCRATCH_TOTAL];

// ---------------- math helpers ---------------------------------------------
__device__ __forceinline__ float geluf(float x) {
    return 0.5f * x * (1.0f + erff(x * 0.70710678118654752f));
}
__device__ __forceinline__ float siluf(float x) {
    return x / (1.0f + __expf(-x));
}
__device__ __forceinline__ float softplusf(float x) {
    return fmaxf(x, 0.0f) + log1pf(__expf(-fabsf(x)));
}

// ---------------- frontend conv0 (1 -> 128 ch, k=5, pad 2) ------------------
__global__ void k_conv0(const float* __restrict__ x, const float* __restrict__ w0,
                        const float* __restrict__ b0, float* __restrict__ out) {
    int idx = blockIdx.x * blockDim.x + threadIdx.x;
    if (idx >= (int)N_CONV) return;
    int t = idx % L_;
    int e = (idx / L_) % E_;
    int b = idx / (L_ * E_);
    float acc = b0[e];
#pragma unroll
    for (int j = 0; j < 5; j++) {
        int ti = t + j - 2;
        if (ti >= 0 && ti < L_) acc += w0[e * 5 + j] * x[b * L_ + ti];
    }
    out[idx] = acc;
}

// ---------------- elementwise gelu ------------------------------------------
__global__ void k_gelu(const float* __restrict__ in, float* __restrict__ out, int n) {
    int idx = blockIdx.x * blockDim.x + threadIdx.x;
    if (idx < n) out[idx] = geluf(in[idx]);
}

// ---------------- dilated conv 128->128, k=5, as tiled GEMM -----------------
// out[b,o,t] = bias[o] + sum_i sum_j g[b,i,t+(j-2)*dil] * W[o,i,j]
__global__ void k_dilconv(const float* __restrict__ g, const float* __restrict__ W,
                          const float* __restrict__ bias, float* __restrict__ out,
                          int dil) {
    __shared__ float Ws[16][65];
    __shared__ float Gs[16][65];
    int b  = blockIdx.z;
    int o0 = blockIdx.y * 64;
    int t0 = blockIdx.x * 64;
    int tid = threadIdx.x;
    int tx = tid & 15, ty = tid >> 4;

    float c[4][4];
#pragma unroll
    for (int i = 0; i < 4; i++)
#pragma unroll
        for (int j = 0; j < 4; j++) c[i][j] = 0.0f;

    for (int kc = 0; kc < 40; kc++) {
        int j   = kc >> 3;            // tap 0..4
        int i0  = (kc & 7) << 4;      // input-channel base
        int off = (j - 2) * dil;
#pragma unroll
        for (int p = 0; p < 4; p++) {
            int idx = tid + p * 256;
            int mm = idx >> 4, kk = idx & 15;
            Ws[kk][mm] = W[(size_t)(o0 + mm) * 640 + (i0 + kk) * 5 + j];
            int ii = idx >> 6, tn = idx & 63;
            int tg = t0 + tn + off;
            Gs[ii][tn] = (tg >= 0 && tg < L_) ? g[((size_t)b * E_ + i0 + ii) * L_ + tg] : 0.0f;
        }
        __syncthreads();
#pragma unroll
        for (int kk = 0; kk < 16; kk++) {
            float a[4], bb[4];
#pragma unroll
            for (int i = 0; i < 4; i++) a[i] = Ws[kk][ty + 16 * i];
#pragma unroll
            for (int j2 = 0; j2 < 4; j2++) bb[j2] = Gs[kk][tx + 16 * j2];
#pragma unroll
            for (int i = 0; i < 4; i++)
#pragma unroll
                for (int j2 = 0; j2 < 4; j2++) c[i][j2] += a[i] * bb[j2];
        }
        __syncthreads();
    }
#pragma unroll
    for (int i = 0; i < 4; i++) {
        int o = o0 + ty + 16 * i;
        float bv = bias[o];
#pragma unroll
        for (int j2 = 0; j2 < 4; j2++) {
            int t = t0 + tx + 16 * j2;
            out[((size_t)b * E_ + o) * L_ + t] = c[i][j2] + bv;
        }
    }
}

// ---------------- residual + transpose + pos_emb ----------------------------
__global__ void k_addtrans(const float* __restrict__ h, const float* __restrict__ x,
                           const float* __restrict__ pos, float* __restrict__ ht) {
    int idx = blockIdx.x * blockDim.x + threadIdx.x;
    if (idx >= (int)N_HT) return;
    int e = idx % E_;
    int bt = idx / E_;
    int t = bt % L_;
    int b = bt / L_;
    ht[idx] = h[((size_t)b * E_ + e) * L_ + t] + x[b * L_ + t] + pos[t * E_ + e];
}

// ---------------- layernorm (one warp per row, E=128) -----------------------
__global__ void k_ln(const float* __restrict__ in, const float* __restrict__ w,
                     const float* __restrict__ bg, float* __restrict__ out) {
    int row = blockIdx.x * 8 + (threadIdx.x >> 5);
    int lane = threadIdx.x & 31;
    const float* p = in + (size_t)row * E_;
    float v[4];
#pragma unroll
    for (int k = 0; k < 4; k++) v[k] = p[lane + 32 * k];
    float s = v[0] + v[1] + v[2] + v[3];
#pragma unroll
    for (int m = 16; m > 0; m >>= 1) s += __shfl_xor_sync(0xffffffffu, s, m);
    float mu = s * (1.0f / 128.0f);
    float q = 0.0f;
#pragma unroll
    for (int k = 0; k < 4; k++) { float d = v[k] - mu; q += d * d; }
#pragma unroll
    for (int m = 16; m > 0; m >>= 1) q += __shfl_xor_sync(0xffffffffu, q, m);
    float inv = rsqrtf(q * (1.0f / 128.0f) + 1e-5f);
#pragma unroll
    for (int k = 0; k < 4; k++) {
        int e = lane + 32 * k;
        out[(size_t)row * E_ + e] = (v[k] - mu) * inv * w[e] + bg[e];
    }
}

// ---------------- generic GEMM: C[n,m] = sum_k X[n,k]*W[m,k] (+res) ---------
__global__ void k_gemm(const float* __restrict__ X, int ldX,
                       const float* __restrict__ W, int Kd, int M,
                       const float* __restrict__ res,
                       float* __restrict__ C, int ldC) {
    __shared__ float Xs[16][65];
    __shared__ float Ws[16][65];
    int n0 = blockIdx.y * 64, m0 = blockIdx.x * 64;
    int tid = threadIdx.x;
    int tx = tid & 15, ty = tid >> 4;

    float c[4][4];
#pragma unroll
    for (int i = 0; i < 4; i++)
#pragma unroll
        for (int j = 0; j < 4; j++) c[i][j] = 0.0f;

    for (int k0 = 0; k0 < Kd; k0 += 16) {
#pragma unroll
        for (int p = 0; p < 4; p++) {
            int idx = tid + p * 256;
            int nn = idx >> 4, kk = idx & 15;
            Xs[kk][nn] = X[(size_t)(n0 + nn) * ldX + k0 + kk];
            Ws[kk][nn] = (m0 + nn < M) ? W[(size_t)(m0 + nn) * Kd + k0 + kk] : 0.0f;
        }
        __syncthreads();
#pragma unroll
        for (int kk = 0; kk < 16; kk++) {
            float a[4], bb[4];
#pragma unroll
            for (int i = 0; i < 4; i++) a[i] = Xs[kk][ty + 16 * i];
#pragma unroll
            for (int j = 0; j < 4; j++) bb[j] = Ws[kk][tx + 16 * j];
#pragma unroll
            for (int i = 0; i < 4; i++)
#pragma unroll
                for (int j = 0; j < 4; j++) c[i][j] += a[i] * bb[j];
        }
        __syncthreads();
    }
#pragma unroll
    for (int i = 0; i < 4; i++) {
        int n = n0 + ty + 16 * i;
#pragma unroll
        for (int j = 0; j < 4; j++) {
            int m = m0 + tx + 16 * j;
            if (m < M) {
                float v = c[i][j];
                if (res) v += res[(size_t)n * ldC + m];
                C[(size_t)n * ldC + m] = v;
            }
        }
    }
}

// ---------------- depthwise causal conv (K=4) + silu; flip folds reverse ----
__global__ void k_dwconv(const float* __restrict__ xz, const float* __restrict__ cw,
                         const float* __restrict__ cb, float* __restrict__ xc, int flip) {
    int idx = blockIdx.x * blockDim.x + threadIdx.x;
    if (idx >= (int)N_XC) return;
    int d = idx % DI;
    int bt = idx / DI;
    int t = bt % L_;
    int b = bt / L_;
    float acc = cb[d];
#pragma unroll
    for (int j = 0; j < KC; j++) {
        int ti = t - 3 + j;
        if (ti >= 0 && ti < L_) {
            int ts = flip ? (L_ - 1 - ti) : ti;
            acc += cw[d * KC + j] * xz[((size_t)(b * L_ + ts)) * (2 * DI) + d];
        }
    }
    xc[idx] = siluf(acc);
}

// ---------------- delta = softplus(dt @ dtw.T + dtb) ------------------------
__global__ void k_delta(const float* __restrict__ xd, const float* __restrict__ dtw,
                        const float* __restrict__ dtb, float* __restrict__ dl) {
    int idx = blockIdx.x * blockDim.x + threadIdx.x;
    if (idx >= (int)N_XC) return;
    int d = idx % DI;
    int bt = idx / DI;
    const float* row = xd + (size_t)bt * XD;
    float acc = dtb[d];
#pragma unroll
    for (int r = 0; r < DTR; r++) acc += row[r] * dtw[d * DTR + r];
    dl[idx] = softplusf(acc);
}

// ---------------- selective scan: warp per (b,d), 48 states in 32 lanes -----
#define TC 32
__global__ void k_scan(const float* __restrict__ xc, const float* __restrict__ dl,
                       const float* __restrict__ xd, const float* __restrict__ Alog,
                       const float* __restrict__ Dp, float* __restrict__ y) {
    __shared__ float sB[TC][DS];
    __shared__ float sC[TC][DS];
    __shared__ float sDel[TC][8];
    __shared__ float sX[TC][8];
    int b  = blockIdx.y;
    int d0 = blockIdx.x * 8;
    int w = threadIdx.x >> 5;
    int lane = threadIdx.x & 31;
    int d = d0 + w;

    float A1 = -expf(Alog[d * DS + lane]);
    float A2 = (lane < 16) ? -expf(Alog[d * DS + lane + 32]) : 0.0f;
    float Dv = Dp[d];
    float h1 = 0.0f, h2 = 0.0f;

    for (int t0 = 0; t0 < L_; t0 += TC) {
        __syncthreads();
        for (int idx = threadIdx.x; idx < TC * 96; idx += 256) {
            int r = idx / 96, cix = idx % 96;
            float v = xd[((size_t)(b * L_ + t0 + r)) * XD + DTR + cix];
            if (cix < DS) sB[r][cix] = v; else sC[r][cix - DS] = v;
        }
        {
            int r = threadIdx.x >> 3, cix = threadIdx.x & 7;
            size_t g = ((size_t)(b * L_ + t0 + r)) * DI + d0 + cix;
            sDel[r][cix] = dl[g];
            sX[r][cix] = xc[g];
        }
        __syncthreads();
#pragma unroll 4
        for (int tt = 0; tt < TC; tt++) {
            float dv = sDel[tt][w], xv = sX[tt][w];
            float dx = dv * xv;
            h1 = __expf(dv * A1) * h1 + dx * sB[tt][lane];
            float p = h1 * sC[tt][lane];
            if (lane < 16) {
                h2 = __expf(dv * A2) * h2 + dx * sB[tt][lane + 32];
                p += h2 * sC[tt][lane + 32];
            }
#pragma unroll
            for (int m = 16; m > 0; m >>= 1) p += __shfl_xor_sync(0xffffffffu, p, m);
            if (lane == 0) y[((size_t)(b * L_ + t0 + tt)) * DI + d] = p + xv * Dv;
        }
    }
}

// ---------------- gate: yg = (yf + flip(yr)) * silu(z) ----------------------
__global__ void k_gate(const float* __restrict__ y0, const float* __restrict__ y1,
                       const float* __restrict__ xz, float* __restrict__ yg) {
    int idx = blockIdx.x * blockDim.x + threadIdx.x;
    if (idx >= (int)N_XC) return;
    int d = idx % DI;
    int bt = idx / DI;
    int t = bt % L_;
    int b = bt / L_;
    float z = xz[(size_t)bt * (2 * DI) + DI + d];
    float v = y0[idx] + y1[((size_t)(b * L_ + (L_ - 1 - t))) * DI + d];
    yg[idx] = v * siluf(z);
}

// ---------------- launcher --------------------------------------------------
extern "C" void kernel_launch(void* const* d_in, const int* in_sizes, int n_in,
                              void* d_out, int out_size) {
    const float* x     = (const float*)d_in[0];
    const float* cw0   = (const float*)d_in[1];
    const float* cb0   = (const float*)d_in[2];
    const float* convw = (const float*)d_in[3];
    const float* convb = (const float*)d_in[4];
    const float* pos   = (const float*)d_in[5];
    const float* lnw   = (const float*)d_in[6];
    const float* lnb   = (const float*)d_in[7];
    const float* ipw   = (const float*)d_in[8];
    const float* opw   = (const float*)d_in[9];
    const float* cw_f  = (const float*)d_in[10];
    const float* cb_f  = (const float*)d_in[11];
    const float* xp_f  = (const float*)d_in[12];
    const float* dtw_f = (const float*)d_in[13];
    const float* dtb_f = (const float*)d_in[14];
    const float* Al_f  = (const float*)d_in[15];
    const float* D_f   = (const float*)d_in[16];
    const float* cw_r  = (const float*)d_in[17];
    const float* cb_r  = (const float*)d_in[18];
    const float* xp_r  = (const float*)d_in[19];
    const float* dtw_r = (const float*)d_in[20];
    const float* dtb_r = (const float*)d_in[21];
    const float* Al_r  = (const float*)d_in[22];
    const float* D_r   = (const float*)d_in[23];
    float* out = (float*)d_out;

    float* S = nullptr;
    cudaGetSymbolAddress((void**)&S, g_scratch);
    float* h0  = S + OFF_H0;
    float* h1  = S + OFF_H1;
    float* gel = S + OFF_GEL;
    float* ht  = S + OFF_HT;
    float* u   = S + OFF_U;
    float* xz  = S + OFF_XZ;
    float* xc0 = S + OFF_XC0;
    float* xc1 = S + OFF_XC1;
    float* xd0 = S + OFF_XD0;
    float* xd1 = S + OFF_XD1;
    float* dl0 = S + OFF_DL0;
    float* dl1 = S + OFF_DL1;
    float* y0  = S + OFF_Y0;
    float* y1  = S + OFF_Y1;
    float* yg  = S + OFF_YG;

    const int TPB = 256;
    int gConv = (int)((N_CONV + TPB - 1) / TPB);
    int gHT   = (int)((N_HT + TPB - 1) / TPB);
    int gXC   = (int)((N_XC + TPB - 1) / TPB);

    // frontend
    k_conv0<<<gConv, TPB>>>(x, cw0, cb0, h0);
    const int dils[4] = {2, 4, 8, 16};
    float* cur = h0;
    float* nxt = h1;
    for (int i = 0; i < 4; i++) {
        k_gelu<<<gConv, TPB>>>(cur, gel, (int)N_CONV);
        k_dilconv<<<dim3(L_ / 64, E_ / 64, B_), TPB>>>(
            gel, convw + (size_t)i * 128 * 128 * 5, convb + i * 128, nxt, dils[i]);
        float* tmp = cur; cur = nxt; nxt = tmp;
    }
    k_addtrans<<<gHT, TPB>>>(cur, x, pos, ht);

    // BiMamba blocks
    for (int blk = 0; blk < 2; blk++) {
        k_ln<<<BL / 8, TPB>>>(ht, lnw + blk * E_, lnb + blk * E_, u);
        k_gemm<<<dim3(8, BL / 64), TPB>>>(u, E_, ipw + (size_t)blk * 2 * DI * E_,
                                          E_, 2 * DI, nullptr, xz, 2 * DI);
        k_dwconv<<<gXC, TPB>>>(xz, cw_f + blk * DI * KC, cb_f + blk * DI, xc0, 0);
        k_dwconv<<<gXC, TPB>>>(xz, cw_r + blk * DI * KC, cb_r + blk * DI, xc1, 1);
        k_gemm<<<dim3(2, BL / 64), TPB>>>(xc0, DI, xp_f + (size_t)blk * XD * DI,
                                          DI, XD, nullptr, xd0, XD);
        k_gemm<<<dim3(2, BL / 64), TPB>>>(xc1, DI, xp_r + (size_t)blk * XD * DI,
                                          DI, XD, nullptr, xd1, XD);
        k_delta<<<gXC, TPB>>>(xd0, dtw_f + blk * DI * DTR, dtb_f + blk * DI, dl0);
        k_delta<<<gXC, TPB>>>(xd1, dtw_r + blk * DI * DTR, dtb_r + blk * DI, dl1);
        k_scan<<<dim3(DI / 8, B_), TPB>>>(xc0, dl0, xd0, Al_f + (size_t)blk * DI * DS,
                                          D_f + blk * DI, y0);
        k_scan<<<dim3(DI / 8, B_), TPB>>>(xc1, dl1, xd1, Al_r + (size_t)blk * DI * DS,
                                          D_r + blk * DI, y1);
        k_gate<<<gXC, TPB>>>(y0, y1, xz, yg);
        float* dst = (blk == 1) ? out : ht;
        k_gemm<<<dim3(2, BL / 64), TPB>>>(yg, DI, opw + (size_t)blk * E_ * DI,
                                          DI, E_, ht, dst, E_);
    }
}

// round 2
// speedup vs baseline: 1.6362x; 1.6362x over previous
#include <cuda_runtime.h>
#include <math.h>
#include <stdint.h>

#define B_  16
#define L_  1024
#define E_  128
#define DI  256
#define DS  48
#define KC  4
#define DTR 8
#define XD  104           // DTR + 2*DS
#define BL  (B_*L_)

// ---------------- scratch (single static device array; no allocation) -------
#define N_CONV   ((size_t)B_*E_*L_)
#define N_HT     ((size_t)BL*E_)
#define N_XZ     ((size_t)BL*2*DI)
#define N_XC     ((size_t)BL*DI)
#define N_XD     ((size_t)BL*XD)

#define OFF_H0   ((size_t)0)
#define OFF_H1   (OFF_H0 + N_CONV)
#define OFF_GEL  (OFF_H1 + N_CONV)
#define OFF_HT   (OFF_GEL + N_CONV)
#define OFF_U    (OFF_HT + N_HT)
#define OFF_XZ   (OFF_U + N_HT)
#define OFF_XC0  (OFF_XZ + N_XZ)
#define OFF_XC1  (OFF_XC0 + N_XC)
#define OFF_XD0  (OFF_XC1 + N_XC)
#define OFF_XD1  (OFF_XD0 + N_XD)
#define OFF_DL0  (OFF_XD1 + N_XD)
#define OFF_DL1  (OFF_DL0 + N_XC)
#define OFF_Y0   (OFF_DL1 + N_XC)
#define OFF_Y1   (OFF_Y0 + N_XC)
#define OFF_YG   (OFF_Y1 + N_XC)
#define SCRATCH_TOTAL (OFF_YG + N_XC)

static __device__ float g_scratch[SCRATCH_TOTAL];

// ---------------- f32x2 helpers ---------------------------------------------
typedef unsigned long long ull;

__device__ __forceinline__ void fma2(ull& d, ull a, ull b) {
    asm("fma.rn.f32x2 %0, %1, %2, %0;" : "+l"(d) : "l"(a), "l"(b));
}
__device__ __forceinline__ void unpack2(ull v, float& lo, float& hi) {
    asm("mov.b64 {%0, %1}, %2;" : "=f"(lo), "=f"(hi) : "l"(v));
}
__device__ __forceinline__ float ex2f(float x) {
    float r; asm("ex2.approx.f32 %0, %1;" : "=f"(r) : "f"(x)); return r;
}

// ---------------- math helpers ----------------------------------------------
__device__ __forceinline__ float geluf(float x) {
    return 0.5f * x * (1.0f + erff(x * 0.70710678118654752f));
}
__device__ __forceinline__ float siluf(float x) {
    return x / (1.0f + __expf(-x));
}
__device__ __forceinline__ float softplusf(float x) {
    return fmaxf(x, 0.0f) + log1pf(__expf(-fabsf(x)));
}

// ---------------- frontend conv0 (1 -> 128 ch, k=5, pad 2) ------------------
__global__ void k_conv0(const float* __restrict__ x, const float* __restrict__ w0,
                        const float* __restrict__ b0, float* __restrict__ out) {
    int idx = blockIdx.x * blockDim.x + threadIdx.x;
    if (idx >= (int)N_CONV) return;
    int t = idx % L_;
    int e = (idx / L_) % E_;
    int b = idx / (L_ * E_);
    float acc = b0[e];
#pragma unroll
    for (int j = 0; j < 5; j++) {
        int ti = t + j - 2;
        if (ti >= 0 && ti < L_) acc += w0[e * 5 + j] * x[b * L_ + ti];
    }
    out[idx] = acc;
}

// ---------------- elementwise gelu ------------------------------------------
__global__ void k_gelu(const float* __restrict__ in, float* __restrict__ out, int n) {
    int idx = blockIdx.x * blockDim.x + threadIdx.x;
    if (idx < n) out[idx] = geluf(in[idx]);
}

// ---------------- dilated conv 128->128, k=5: 128x128 tile, FFMA2 ----------
// out[b,o,t] = bias[o] + sum_{i,j} gel[b,i,t+(j-2)*dil] * W[o, i*5+j]
__global__ void __launch_bounds__(256) k_dilconv(
        const float* __restrict__ g, const float* __restrict__ W,
        const float* __restrict__ bias, float* __restrict__ out, int dil) {
    __shared__ float Xs2[16][264];   // t-dim, duplicated pairs
    __shared__ float Ws[16][132];    // o-dim
    int b  = blockIdx.z;
    int t0 = blockIdx.x * 128;
    int tid = threadIdx.x;
    int tx = tid & 15, ty = tid >> 4;

    ull acc[8][4];
#pragma unroll
    for (int i = 0; i < 8; i++)
#pragma unroll
        for (int j = 0; j < 4; j++) acc[i][j] = 0ull;

    for (int k0 = 0; k0 < 640; k0 += 16) {
        // X gather (t rows x 16 k), scalar, gelu'd input already in g
#pragma unroll
        for (int p = 0; p < 8; p++) {
            int idx = tid + p * 256;
            int tn = idx & 127, kq = idx >> 7;
            int kg = k0 + kq;
            int ci = kg / 5;
            int j  = kg - ci * 5;
            int tg = t0 + tn + (j - 2) * dil;
            float v = (tg >= 0 && tg < L_) ? g[((size_t)b * E_ + ci) * L_ + tg] : 0.0f;
            Xs2[kq][2 * tn] = v;
            Xs2[kq][2 * tn + 1] = v;
        }
        // W (128 o x 16 k) vectorized
#pragma unroll
        for (int p = 0; p < 2; p++) {
            int idx = tid + p * 256;
            int row = idx >> 2, kv = idx & 3;
            float4 v = *(const float4*)&W[(size_t)row * 640 + k0 + kv * 4];
            Ws[kv * 4 + 0][row] = v.x;
            Ws[kv * 4 + 1][row] = v.y;
            Ws[kv * 4 + 2][row] = v.z;
            Ws[kv * 4 + 3][row] = v.w;
        }
        __syncthreads();
#pragma unroll
        for (int kk = 0; kk < 16; kk++) {
            const ulonglong2* ap = (const ulonglong2*)&Xs2[kk][ty * 16];
            const ulonglong2* bp = (const ulonglong2*)&Ws[kk][tx * 8];
            ulonglong2 a01 = ap[0], a23 = ap[1], a45 = ap[2], a67 = ap[3];
            ulonglong2 b03 = bp[0], b47 = bp[1];
            ull av[8] = {a01.x, a01.y, a23.x, a23.y, a45.x, a45.y, a67.x, a67.y};
            ull bv[4] = {b03.x, b03.y, b47.x, b47.y};
#pragma unroll
            for (int i = 0; i < 8; i++)
#pragma unroll
                for (int j = 0; j < 4; j++) fma2(acc[i][j], av[i], bv[j]);
        }
        __syncthreads();
    }
    // epilogue: out is o-major [b,o,t]
#pragma unroll
    for (int i = 0; i < 8; i++) {
        int t = t0 + ty * 8 + i;
#pragma unroll
        for (int j = 0; j < 4; j++) {
            float lo, hi; unpack2(acc[i][j], lo, hi);
            int o = tx * 8 + 2 * j;
            out[((size_t)b * E_ + o) * L_ + t]     = lo + bias[o];
            out[((size_t)b * E_ + o + 1) * L_ + t] = hi + bias[o + 1];
        }
    }
}

// ---------------- residual + transpose + pos_emb ----------------------------
__global__ void k_addtrans(const float* __restrict__ h, const float* __restrict__ x,
                           const float* __restrict__ pos, float* __restrict__ ht) {
    int idx = blockIdx.x * blockDim.x + threadIdx.x;
    if (idx >= (int)N_HT) return;
    int e = idx % E_;
    int bt = idx / E_;
    int t = bt % L_;
    int b = bt / L_;
    ht[idx] = h[((size_t)b * E_ + e) * L_ + t] + x[b * L_ + t] + pos[t * E_ + e];
}

// ---------------- layernorm (one warp per row, E=128) -----------------------
__global__ void k_ln(const float* __restrict__ in, const float* __restrict__ w,
                     const float* __restrict__ bg, float* __restrict__ out) {
    int row = blockIdx.x * 8 + (threadIdx.x >> 5);
    int lane = threadIdx.x & 31;
    const float* p = in + (size_t)row * E_;
    float v[4];
#pragma unroll
    for (int k = 0; k < 4; k++) v[k] = p[lane + 32 * k];
    float s = v[0] + v[1] + v[2] + v[3];
#pragma unroll
    for (int m = 16; m > 0; m >>= 1) s += __shfl_xor_sync(0xffffffffu, s, m);
    float mu = s * (1.0f / 128.0f);
    float q = 0.0f;
#pragma unroll
    for (int k = 0; k < 4; k++) { float d = v[k] - mu; q += d * d; }
#pragma unroll
    for (int m = 16; m > 0; m >>= 1) q += __shfl_xor_sync(0xffffffffu, q, m);
    float inv = rsqrtf(q * (1.0f / 128.0f) + 1e-5f);
#pragma unroll
    for (int k = 0; k < 4; k++) {
        int e = lane + 32 * k;
        out[(size_t)row * E_ + e] = (v[k] - mu) * inv * w[e] + bg[e];
    }
}

// ---------------- 128x128-tile GEMM with FFMA2: C[n,m]=X[n,:]W[m,:]+res -----
struct GP { const float* X; const float* W; const float* res; float* C; };

__global__ void __launch_bounds__(256) k_gemm128(
        GP pa, GP pb, int ldX, int Kd, int M, int ldC) {
    GP p = blockIdx.z ? pb : pa;
    __shared__ float Xs2[16][264];
    __shared__ float Ws[16][132];
    int n0 = blockIdx.y * 128, m0 = blockIdx.x * 128;
    int tid = threadIdx.x;
    int tx = tid & 15, ty = tid >> 4;

    ull acc[8][4];
#pragma unroll
    for (int i = 0; i < 8; i++)
#pragma unroll
        for (int j = 0; j < 4; j++) acc[i][j] = 0ull;

    for (int k0 = 0; k0 < Kd; k0 += 16) {
#pragma unroll
        for (int pq = 0; pq < 2; pq++) {
            int idx = tid + pq * 256;
            int row = idx >> 2, kv = idx & 3;
            float4 v = *(const float4*)&p.X[(size_t)(n0 + row) * ldX + k0 + kv * 4];
            int c2 = 2 * row;
            Xs2[kv * 4 + 0][c2] = v.x; Xs2[kv * 4 + 0][c2 + 1] = v.x;
            Xs2[kv * 4 + 1][c2] = v.y; Xs2[kv * 4 + 1][c2 + 1] = v.y;
            Xs2[kv * 4 + 2][c2] = v.z; Xs2[kv * 4 + 2][c2 + 1] = v.z;
            Xs2[kv * 4 + 3][c2] = v.w; Xs2[kv * 4 + 3][c2 + 1] = v.w;
        }
#pragma unroll
        for (int pq = 0; pq < 2; pq++) {
            int idx = tid + pq * 256;
            int row = idx >> 2, kv = idx & 3;
            int m = m0 + row;
            float4 v = make_float4(0.f, 0.f, 0.f, 0.f);
            if (m < M) v = *(const float4*)&p.W[(size_t)m * Kd + k0 + kv * 4];
            Ws[kv * 4 + 0][row] = v.x;
            Ws[kv * 4 + 1][row] = v.y;
            Ws[kv * 4 + 2][row] = v.z;
            Ws[kv * 4 + 3][row] = v.w;
        }
        __syncthreads();
#pragma unroll
        for (int kk = 0; kk < 16; kk++) {
            const ulonglong2* ap = (const ulonglong2*)&Xs2[kk][ty * 16];
            const ulonglong2* bp = (const ulonglong2*)&Ws[kk][tx * 8];
            ulonglong2 a01 = ap[0], a23 = ap[1], a45 = ap[2], a67 = ap[3];
            ulonglong2 b03 = bp[0], b47 = bp[1];
            ull av[8] = {a01.x, a01.y, a23.x, a23.y, a45.x, a45.y, a67.x, a67.y};
            ull bv[4] = {b03.x, b03.y, b47.x, b47.y};
#pragma unroll
            for (int i = 0; i < 8; i++)
#pragma unroll
                for (int j = 0; j < 4; j++) fma2(acc[i][j], av[i], bv[j]);
        }
        __syncthreads();
    }
#pragma unroll
    for (int i = 0; i < 8; i++) {
        int n = n0 + ty * 8 + i;
        float* crow = p.C + (size_t)n * ldC;
        const float* rrow = p.res ? p.res + (size_t)n * ldC : nullptr;
#pragma unroll
        for (int j = 0; j < 4; j++) {
            float lo, hi; unpack2(acc[i][j], lo, hi);
            int m = m0 + tx * 8 + 2 * j;
            if (m < M)     crow[m]     = lo + (rrow ? rrow[m] : 0.0f);
            if (m + 1 < M) crow[m + 1] = hi + (rrow ? rrow[m + 1] : 0.0f);
        }
    }
}

// ---------------- depthwise causal conv (K=4) + silu; f/r paired on z -------
struct DWP { const float* cw; const float* cb; float* xc; int flip; };
__global__ void k_dwconv(const float* __restrict__ xz, DWP a, DWP b) {
    DWP p = blockIdx.z ? b : a;
    int idx = blockIdx.x * blockDim.x + threadIdx.x;
    if (idx >= (int)N_XC) return;
    int d = idx % DI;
    int bt = idx / DI;
    int t = bt % L_;
    int bb = bt / L_;
    float acc = p.cb[d];
#pragma unroll
    for (int j = 0; j < KC; j++) {
        int ti = t - 3 + j;
        if (ti >= 0 && ti < L_) {
            int ts = p.flip ? (L_ - 1 - ti) : ti;
            acc += p.cw[d * KC + j] * xz[((size_t)(bb * L_ + ts)) * (2 * DI) + d];
        }
    }
    p.xc[idx] = siluf(acc);
}

// ---------------- delta = softplus(dt @ dtw.T + dtb); f/r paired on z -------
struct DLP { const float* xd; const float* dtw; const float* dtb; float* dl; };
__global__ void k_delta(DLP a, DLP b) {
    DLP p = blockIdx.z ? b : a;
    int idx = blockIdx.x * blockDim.x + threadIdx.x;
    if (idx >= (int)N_XC) return;
    int d = idx % DI;
    int bt = idx / DI;
    const float* row = p.xd + (size_t)bt * XD;
    float acc = p.dtb[d];
#pragma unroll
    for (int r = 0; r < DTR; r++) acc += row[r] * p.dtw[d * DTR + r];
    p.dl[idx] = softplusf(acc);
}

// ---------------- selective scan: 8 threads per (b,d), 6 states each --------
struct SCP { const float* xc; const float* dl; const float* xd;
             const float* Al; const float* Dp; float* y; };
#define SCT 32
__global__ void __launch_bounds__(256) k_scan(SCP pa, SCP pb) {
    SCP p = blockIdx.z ? pb : pa;
    __shared__ float sB[SCT][DS];
    __shared__ float sC[SCT][DS];
    __shared__ float sDel[SCT][32];
    __shared__ float sX[SCT][32];
    int b = blockIdx.y;
    int dbase = blockIdx.x * 32;
    int tid = threadIdx.x;
    int lane = tid & 31, w = tid >> 5;
    int grp = lane >> 3, sub = lane & 7;
    int d = dbase + w * 4 + grp;
    int di = w * 4 + grp;

    float A[6], h[6];
#pragma unroll
    for (int q = 0; q < 6; q++) {
        A[q] = -expf(p.Al[d * DS + sub * 6 + q]) * 1.4426950408889634f;
        h[q] = 0.0f;
    }
    float Dv = p.Dp[d];

    for (int t0 = 0; t0 < L_; t0 += SCT) {
        __syncthreads();
        for (int i = tid; i < SCT * 96; i += 256) {
            int r = i / 96, c = i - r * 96;
            float v = p.xd[(size_t)(b * L_ + t0 + r) * XD + DTR + c];
            if (c < DS) sB[r][c] = v; else sC[r][c - DS] = v;
        }
        for (int i = tid; i < SCT * 32; i += 256) {
            int r = i >> 5, c = i & 31;
            size_t g = (size_t)(b * L_ + t0 + r) * DI + dbase + c;
            sDel[r][c] = p.dl[g];
            sX[r][c]   = p.xc[g];
        }
        __syncthreads();
#pragma unroll 4
        for (int tt = 0; tt < SCT; tt++) {
            float dv = sDel[tt][di], xv = sX[tt][di];
            float dx = dv * xv;
            const float2* Bp = (const float2*)&sB[tt][sub * 6];
            const float2* Cp = (const float2*)&sC[tt][sub * 6];
            float2 B0 = Bp[0], B1 = Bp[1], B2 = Bp[2];
            float2 C0 = Cp[0], C1 = Cp[1], C2 = Cp[2];
            float pr = 0.0f;
            h[0] = ex2f(dv * A[0]) * h[0] + dx * B0.x; pr = fmaf(h[0], C0.x, pr);
            h[1] = ex2f(dv * A[1]) * h[1] + dx * B0.y; pr = fmaf(h[1], C0.y, pr);
            h[2] = ex2f(dv * A[2]) * h[2] + dx * B1.x; pr = fmaf(h[2], C1.x, pr);
            h[3] = ex2f(dv * A[3]) * h[3] + dx * B1.y; pr = fmaf(h[3], C1.y, pr);
            h[4] = ex2f(dv * A[4]) * h[4] + dx * B2.x; pr = fmaf(h[4], C2.x, pr);
            h[5] = ex2f(dv * A[5]) * h[5] + dx * B2.y; pr = fmaf(h[5], C2.y, pr);
            pr += __shfl_xor_sync(0xffffffffu, pr, 1);
            pr += __shfl_xor_sync(0xffffffffu, pr, 2);
            pr += __shfl_xor_sync(0xffffffffu, pr, 4);
            if (sub == 0)
                p.y[(size_t)(b * L_ + t0 + tt) * DI + d] = pr + xv * Dv;
        }
    }
}

// ---------------- gate: yg = (yf + flip(yr)) * silu(z) ----------------------
__global__ void k_gate(const float* __restrict__ y0, const float* __restrict__ y1,
                       const float* __restrict__ xz, float* __restrict__ yg) {
    int idx = blockIdx.x * blockDim.x + threadIdx.x;
    if (idx >= (int)N_XC) return;
    int d = idx % DI;
    int bt = idx / DI;
    int t = bt % L_;
    int b = bt / L_;
    float z = xz[(size_t)bt * (2 * DI) + DI + d];
    float v = y0[idx] + y1[((size_t)(b * L_ + (L_ - 1 - t))) * DI + d];
    yg[idx] = v * siluf(z);
}

// ---------------- launcher --------------------------------------------------
extern "C" void kernel_launch(void* const* d_in, const int* in_sizes, int n_in,
                              void* d_out, int out_size) {
    const float* x     = (const float*)d_in[0];
    const float* cw0   = (const float*)d_in[1];
    const float* cb0   = (const float*)d_in[2];
    const float* convw = (const float*)d_in[3];
    const float* convb = (const float*)d_in[4];
    const float* pos   = (const float*)d_in[5];
    const float* lnw   = (const float*)d_in[6];
    const float* lnb   = (const float*)d_in[7];
    const float* ipw   = (const float*)d_in[8];
    const float* opw   = (const float*)d_in[9];
    const float* cw_f  = (const float*)d_in[10];
    const float* cb_f  = (const float*)d_in[11];
    const float* xp_f  = (const float*)d_in[12];
    const float* dtw_f = (const float*)d_in[13];
    const float* dtb_f = (const float*)d_in[14];
    const float* Al_f  = (const float*)d_in[15];
    const float* D_f   = (const float*)d_in[16];
    const float* cw_r  = (const float*)d_in[17];
    const float* cb_r  = (const float*)d_in[18];
    const float* xp_r  = (const float*)d_in[19];
    const float* dtw_r = (const float*)d_in[20];
    const float* dtb_r = (const float*)d_in[21];
    const float* Al_r  = (const float*)d_in[22];
    const float* D_r   = (const float*)d_in[23];
    float* out = (float*)d_out;

    float* S = nullptr;
    cudaGetSymbolAddress((void**)&S, g_scratch);
    float* h0  = S + OFF_H0;
    float* h1  = S + OFF_H1;
    float* gel = S + OFF_GEL;
    float* ht  = S + OFF_HT;
    float* u   = S + OFF_U;
    float* xz  = S + OFF_XZ;
    float* xc0 = S + OFF_XC0;
    float* xc1 = S + OFF_XC1;
    float* xd0 = S + OFF_XD0;
    float* xd1 = S + OFF_XD1;
    float* dl0 = S + OFF_DL0;
    float* dl1 = S + OFF_DL1;
    float* y0  = S + OFF_Y0;
    float* y1  = S + OFF_Y1;
    float* yg  = S + OFF_YG;

    const int TPB = 256;
    int gConv = (int)((N_CONV + TPB - 1) / TPB);
    int gHT   = (int)((N_HT + TPB - 1) / TPB);
    int gXC   = (int)((N_XC + TPB - 1) / TPB);

    // frontend
    k_conv0<<<gConv, TPB>>>(x, cw0, cb0, h0);
    const int dils[4] = {2, 4, 8, 16};
    float* cur = h0;
    float* nxt = h1;
    for (int i = 0; i < 4; i++) {
        k_gelu<<<gConv, TPB>>>(cur, gel, (int)N_CONV);
        k_dilconv<<<dim3(L_ / 128, 1, B_), TPB>>>(
            gel, convw + (size_t)i * 128 * 128 * 5, convb + i * 128, nxt, dils[i]);
        float* tmp = cur; cur = nxt; nxt = tmp;
    }
    k_addtrans<<<gHT, TPB>>>(cur, x, pos, ht);

    // BiMamba blocks
    for (int blk = 0; blk < 2; blk++) {
        k_ln<<<BL / 8, TPB>>>(ht, lnw + blk * E_, lnb + blk * E_, u);

        GP ip{u, ipw + (size_t)blk * 2 * DI * E_, nullptr, xz};
        k_gemm128<<<dim3(4, BL / 128, 1), TPB>>>(ip, ip, E_, E_, 2 * DI, 2 * DI);

        DWP dwa{cw_f + blk * DI * KC, cb_f + blk * DI, xc0, 0};
        DWP dwb{cw_r + blk * DI * KC, cb_r + blk * DI, xc1, 1};
        k_dwconv<<<dim3(gXC, 1, 2), TPB>>>(xz, dwa, dwb);

        GP xa{xc0, xp_f + (size_t)blk * XD * DI, nullptr, xd0};
        GP xb{xc1, xp_r + (size_t)blk * XD * DI, nullptr, xd1};
        k_gemm128<<<dim3(1, BL / 128, 2), TPB>>>(xa, xb, DI, DI, XD, XD);

        DLP dla{xd0, dtw_f + blk * DI * DTR, dtb_f + blk * DI, dl0};
        DLP dlb{xd1, dtw_r + blk * DI * DTR, dtb_r + blk * DI, dl1};
        k_delta<<<dim3(gXC, 1, 2), TPB>>>(dla, dlb);

        SCP sa{xc0, dl0, xd0, Al_f + (size_t)blk * DI * DS, D_f + blk * DI, y0};
        SCP sb{xc1, dl1, xd1, Al_r + (size_t)blk * DI * DS, D_r + blk * DI, y1};
        k_scan<<<dim3(DI / 32, B_, 2), TPB>>>(sa, sb);

        k_gate<<<gXC, TPB>>>(y0, y1, xz, yg);

        float* dst = (blk == 1) ? out : ht;
        GP op{yg, opw + (size_t)blk * E_ * DI, ht, dst};
        k_gemm128<<<dim3(1, BL / 128, 1), TPB>>>(op, op, DI, DI, E_, E_);
    }
}

// round 3
// speedup vs baseline: 1.7637x; 1.0779x over previous
#include <cuda_runtime.h>
#include <math.h>
#include <stdint.h>

#define B_  16
#define L_  1024
#define E_  128
#define DI  256
#define DS  48
#define KC  4
#define DTR 8
#define XD  104           // DTR + 2*DS
#define BL  (B_*L_)

// ---------------- scratch ----------------------------------------------------
#define N_CONV   ((size_t)B_*E_*L_)
#define N_HT     ((size_t)BL*E_)
#define N_XZ     ((size_t)BL*2*DI)
#define N_XC     ((size_t)BL*DI)
#define N_XD     ((size_t)BL*XD)

#define OFF_GA   ((size_t)0)
#define OFF_GB   (OFF_GA + N_CONV)
#define OFF_HT   (OFF_GB + N_CONV)
#define OFF_U    (OFF_HT + N_HT)
#define OFF_XZ   (OFF_U + N_HT)
#define OFF_XC0  (OFF_XZ + N_XZ)
#define OFF_XC1  (OFF_XC0 + N_XC)
#define OFF_XD0  (OFF_XC1 + N_XC)
#define OFF_XD1  (OFF_XD0 + N_XD)
#define OFF_Y0   (OFF_XD1 + N_XD)
#define OFF_Y1   (OFF_Y0 + N_XC)
#define SCRATCH_TOTAL (OFF_Y1 + N_XC)

static __device__ float g_scratch[SCRATCH_TOTAL];

// ---------------- helpers ----------------------------------------------------
typedef unsigned long long ull;

__device__ __forceinline__ void fma2(ull& d, ull a, ull b) {
    asm("fma.rn.f32x2 %0, %1, %2, %0;" : "+l"(d) : "l"(a), "l"(b));
}
__device__ __forceinline__ void unpack2(ull v, float& lo, float& hi) {
    asm("mov.b64 {%0, %1}, %2;" : "=f"(lo), "=f"(hi) : "l"(v));
}
__device__ __forceinline__ float ex2f(float x) {
    float r; asm("ex2.approx.f32 %0, %1;" : "=f"(r) : "f"(x)); return r;
}
__device__ __forceinline__ float geluf(float x) {
    return 0.5f * x * (1.0f + erff(x * 0.70710678118654752f));
}
__device__ __forceinline__ float siluf(float x) {
    return x / (1.0f + __expf(-x));
}
__device__ __forceinline__ float softplusf(float x) {
    return fmaxf(x, 0.0f) + log1pf(__expf(-fabsf(x)));
}

// ============================================================================
// Dilated conv chain: 128x128 output tile (t x o), FFMA2, double-buffered.
// FUSE0: input = gelu(conv0(x)) computed inline.  MODE 0: out = gelu(conv+b),
// layout [b,o,t].  MODE 1: out = ht[b,t,o] = conv+b + x[b,t] + pos[t,o].
// ============================================================================
template <int FUSE0, int MODE>
__global__ void __launch_bounds__(256) k_dilconv(
        const float* __restrict__ g, const float* __restrict__ W,
        const float* __restrict__ bias, float* __restrict__ out, int dil,
        const float* __restrict__ x, const float* __restrict__ w0,
        const float* __restrict__ b0, const float* __restrict__ pos) {
    __shared__ float Xs2[2][16][264];
    __shared__ float Ws[2][16][132];
    int b  = blockIdx.z;
    int t0 = blockIdx.x * 128;
    int tid = threadIdx.x;
    int tx = tid & 15, ty = tid >> 4;
    int tn = tid & 127;           // fixed per thread
    int kqb = tid >> 7;           // 0 or 1

    ull acc[8][4];
#pragma unroll
    for (int i = 0; i < 8; i++)
#pragma unroll
        for (int j = 0; j < 4; j++) acc[i][j] = 0ull;

    auto LD = [&](int k0, float xr[8], float4 wf[2]) {
#pragma unroll
        for (int p = 0; p < 8; p++) {
            int kq = kqb + 2 * p;
            int kg = k0 + kq;
            int ci = kg / 5;
            int j  = kg - ci * 5;
            int tg = t0 + tn + (j - 2) * dil;
            float v = 0.0f;
            if (tg >= 0 && tg < L_) {
                if (FUSE0) {
                    float a = b0[ci];
#pragma unroll
                    for (int j2 = 0; j2 < 5; j2++) {
                        int ti = tg + j2 - 2;
                        if (ti >= 0 && ti < L_) a += w0[ci * 5 + j2] * x[b * L_ + ti];
                    }
                    v = geluf(a);
                } else {
                    v = g[((size_t)b * E_ + ci) * L_ + tg];
                }
            }
            xr[p] = v;
        }
#pragma unroll
        for (int p = 0; p < 2; p++) {
            int idx = tid + p * 256;
            int row = idx >> 2, kv = idx & 3;
            wf[p] = *(const float4*)&W[(size_t)row * 640 + k0 + kv * 4];
        }
    };
    auto ST = [&](int s, float xr[8], float4 wf[2]) {
#pragma unroll
        for (int p = 0; p < 8; p++) {
            int kq = kqb + 2 * p;
            float v = xr[p];
            *(float2*)&Xs2[s][kq][2 * tn] = make_float2(v, v);
        }
#pragma unroll
        for (int p = 0; p < 2; p++) {
            int idx = tid + p * 256;
            int row = idx >> 2, kv = idx & 3;
            Ws[s][kv * 4 + 0][row] = wf[p].x;
            Ws[s][kv * 4 + 1][row] = wf[p].y;
            Ws[s][kv * 4 + 2][row] = wf[p].z;
            Ws[s][kv * 4 + 3][row] = wf[p].w;
        }
    };

    float xr[8]; float4 wf[2];
    LD(0, xr, wf);
    ST(0, xr, wf);
    __syncthreads();

    const int NK = 40;
    for (int kt = 0; kt < NK; kt++) {
        int cur = kt & 1;
        float xr2[8]; float4 wf2[2];
        if (kt + 1 < NK) LD((kt + 1) * 16, xr2, wf2);
#pragma unroll
        for (int kk = 0; kk < 16; kk++) {
            const ulonglong2* ap = (const ulonglong2*)&Xs2[cur][kk][ty * 16];
            const ulonglong2* bp = (const ulonglong2*)&Ws[cur][kk][tx * 8];
            ulonglong2 a01 = ap[0], a23 = ap[1], a45 = ap[2], a67 = ap[3];
            ulonglong2 b03 = bp[0], b47 = bp[1];
            ull av[8] = {a01.x, a01.y, a23.x, a23.y, a45.x, a45.y, a67.x, a67.y};
            ull bv[4] = {b03.x, b03.y, b47.x, b47.y};
#pragma unroll
            for (int i = 0; i < 8; i++)
#pragma unroll
                for (int j = 0; j < 4; j++) fma2(acc[i][j], av[i], bv[j]);
        }
        if (kt + 1 < NK) ST(1 - cur, xr2, wf2);
        __syncthreads();
    }

#pragma unroll
    for (int i = 0; i < 8; i++) {
        int t = t0 + ty * 8 + i;
#pragma unroll
        for (int j = 0; j < 4; j++) {
            float lo, hi; unpack2(acc[i][j], lo, hi);
            int o = tx * 8 + 2 * j;
            if (MODE == 0) {
                out[((size_t)b * E_ + o) * L_ + t]     = geluf(lo + bias[o]);
                out[((size_t)b * E_ + o + 1) * L_ + t] = geluf(hi + bias[o + 1]);
            } else {
                float xb = x[b * L_ + t];
                out[((size_t)(b * L_ + t)) * E_ + o]     = lo + bias[o]     + xb + pos[t * E_ + o];
                out[((size_t)(b * L_ + t)) * E_ + o + 1] = hi + bias[o + 1] + xb + pos[t * E_ + o + 1];
            }
        }
    }
}

// ---------------- layernorm (one warp per row, E=128) -----------------------
__global__ void k_ln(const float* __restrict__ in, const float* __restrict__ w,
                     const float* __restrict__ bg, float* __restrict__ out) {
    int row = blockIdx.x * 8 + (threadIdx.x >> 5);
    int lane = threadIdx.x & 31;
    const float* p = in + (size_t)row * E_;
    float v[4];
#pragma unroll
    for (int k = 0; k < 4; k++) v[k] = p[lane + 32 * k];
    float s = v[0] + v[1] + v[2] + v[3];
#pragma unroll
    for (int m = 16; m > 0; m >>= 1) s += __shfl_xor_sync(0xffffffffu, s, m);
    float mu = s * (1.0f / 128.0f);
    float q = 0.0f;
#pragma unroll
    for (int k = 0; k < 4; k++) { float d = v[k] - mu; q += d * d; }
#pragma unroll
    for (int m = 16; m > 0; m >>= 1) q += __shfl_xor_sync(0xffffffffu, q, m);
    float inv = rsqrtf(q * (1.0f / 128.0f) + 1e-5f);
#pragma unroll
    for (int k = 0; k < 4; k++) {
        int e = lane + 32 * k;
        out[(size_t)row * E_ + e] = (v[k] - mu) * inv * w[e] + bg[e];
    }
}

// ============================================================================
// 128x128-tile GEMM, FFMA2, double-buffered. C[n,m] = X[n,:].W[m,:] (+res)
// ============================================================================
struct GP { const float* X; const float* W; const float* res; float* C; };

__global__ void __launch_bounds__(256) k_gemm128(
        GP pa, GP pb, int ldX, int Kd, int M, int ldC) {
    GP p = blockIdx.z ? pb : pa;
    __shared__ float Xs2[2][16][264];
    __shared__ float Ws[2][16][132];
    int n0 = blockIdx.y * 128, m0 = blockIdx.x * 128;
    int tid = threadIdx.x;
    int tx = tid & 15, ty = tid >> 4;

    ull acc[8][4];
#pragma unroll
    for (int i = 0; i < 8; i++)
#pragma unroll
        for (int j = 0; j < 4; j++) acc[i][j] = 0ull;

    auto LD = [&](int k0, float4 xf[2], float4 wf[2]) {
#pragma unroll
        for (int pq = 0; pq < 2; pq++) {
            int idx = tid + pq * 256;
            int row = idx >> 2, kv = idx & 3;
            xf[pq] = *(const float4*)&p.X[(size_t)(n0 + row) * ldX + k0 + kv * 4];
            int m = m0 + row;
            wf[pq] = (m < M) ? *(const float4*)&p.W[(size_t)m * Kd + k0 + kv * 4]
                             : make_float4(0.f, 0.f, 0.f, 0.f);
        }
    };
    auto ST = [&](int s, float4 xf[2], float4 wf[2]) {
#pragma unroll
        for (int pq = 0; pq < 2; pq++) {
            int idx = tid + pq * 256;
            int row = idx >> 2, kv = idx & 3;
            float vx[4] = {xf[pq].x, xf[pq].y, xf[pq].z, xf[pq].w};
#pragma unroll
            for (int q = 0; q < 4; q++)
                *(float2*)&Xs2[s][kv * 4 + q][2 * row] = make_float2(vx[q], vx[q]);
            Ws[s][kv * 4 + 0][row] = wf[pq].x;
            Ws[s][kv * 4 + 1][row] = wf[pq].y;
            Ws[s][kv * 4 + 2][row] = wf[pq].z;
            Ws[s][kv * 4 + 3][row] = wf[pq].w;
        }
    };

    float4 xf[2], wf[2];
    LD(0, xf, wf);
    ST(0, xf, wf);
    __syncthreads();

    int nk = Kd >> 4;
    for (int kt = 0; kt < nk; kt++) {
        int cur = kt & 1;
        float4 xf2[2], wf2[2];
        if (kt + 1 < nk) LD((kt + 1) * 16, xf2, wf2);
#pragma unroll
        for (int kk = 0; kk < 16; kk++) {
            const ulonglong2* ap = (const ulonglong2*)&Xs2[cur][kk][ty * 16];
            const ulonglong2* bp = (const ulonglong2*)&Ws[cur][kk][tx * 8];
            ulonglong2 a01 = ap[0], a23 = ap[1], a45 = ap[2], a67 = ap[3];
            ulonglong2 b03 = bp[0], b47 = bp[1];
            ull av[8] = {a01.x, a01.y, a23.x, a23.y, a45.x, a45.y, a67.x, a67.y};
            ull bv[4] = {b03.x, b03.y, b47.x, b47.y};
#pragma unroll
            for (int i = 0; i < 8; i++)
#pragma unroll
                for (int j = 0; j < 4; j++) fma2(acc[i][j], av[i], bv[j]);
        }
        if (kt + 1 < nk) ST(1 - cur, xf2, wf2);
        __syncthreads();
    }

#pragma unroll
    for (int i = 0; i < 8; i++) {
        int n = n0 + ty * 8 + i;
        float* crow = p.C + (size_t)n * ldC;
        const float* rrow = p.res ? p.res + (size_t)n * ldC : nullptr;
#pragma unroll
        for (int j = 0; j < 4; j++) {
            float lo, hi; unpack2(acc[i][j], lo, hi);
            int m = m0 + tx * 8 + 2 * j;
            if (m < M)     crow[m]     = lo + (rrow ? rrow[m] : 0.0f);
            if (m + 1 < M) crow[m + 1] = hi + (rrow ? rrow[m + 1] : 0.0f);
        }
    }
}

// ============================================================================
// out_proj GEMM with fused gate-gather: X[n,k] = (y0[n,k]+y1[flip,k])*silu(z)
// M = 128 (one m-tile) so each X element is gathered exactly once.
// ============================================================================
__global__ void __launch_bounds__(256) k_gemm_out(
        const float* __restrict__ y0, const float* __restrict__ y1,
        const float* __restrict__ xz, const float* __restrict__ W,
        const float* __restrict__ res, float* __restrict__ C) {
    __shared__ float Xs2[2][16][264];
    __shared__ float Ws[2][16][132];
    int n0 = blockIdx.y * 128;
    int tid = threadIdx.x;
    int tx = tid & 15, ty = tid >> 4;

    ull acc[8][4];
#pragma unroll
    for (int i = 0; i < 8; i++)
#pragma unroll
        for (int j = 0; j < 4; j++) acc[i][j] = 0ull;

    auto LD = [&](int k0, float4 xf[2], float4 wf[2]) {
#pragma unroll
        for (int pq = 0; pq < 2; pq++) {
            int idx = tid + pq * 256;
            int row = idx >> 2, kv = idx & 3;
            int n = n0 + row;
            int b = n >> 10, t = n & 1023;
            int k = k0 + kv * 4;
            float4 a = *(const float4*)&y0[(size_t)n * DI + k];
            float4 c = *(const float4*)&y1[((size_t)(b * L_ + (L_ - 1 - t))) * DI + k];
            float4 z = *(const float4*)&xz[(size_t)n * (2 * DI) + DI + k];
            xf[pq].x = (a.x + c.x) * siluf(z.x);
            xf[pq].y = (a.y + c.y) * siluf(z.y);
            xf[pq].z = (a.z + c.z) * siluf(z.z);
            xf[pq].w = (a.w + c.w) * siluf(z.w);
            wf[pq] = *(const float4*)&W[(size_t)row * DI + k];
        }
    };
    auto ST = [&](int s, float4 xf[2], float4 wf[2]) {
#pragma unroll
        for (int pq = 0; pq < 2; pq++) {
            int idx = tid + pq * 256;
            int row = idx >> 2, kv = idx & 3;
            float vx[4] = {xf[pq].x, xf[pq].y, xf[pq].z, xf[pq].w};
#pragma unroll
            for (int q = 0; q < 4; q++)
                *(float2*)&Xs2[s][kv * 4 + q][2 * row] = make_float2(vx[q], vx[q]);
            Ws[s][kv * 4 + 0][row] = wf[pq].x;
            Ws[s][kv * 4 + 1][row] = wf[pq].y;
            Ws[s][kv * 4 + 2][row] = wf[pq].z;
            Ws[s][kv * 4 + 3][row] = wf[pq].w;
        }
    };

    float4 xf[2], wf[2];
    LD(0, xf, wf);
    ST(0, xf, wf);
    __syncthreads();

    const int NK = DI / 16;
    for (int kt = 0; kt < NK; kt++) {
        int cur = kt & 1;
        float4 xf2[2], wf2[2];
        if (kt + 1 < NK) LD((kt + 1) * 16, xf2, wf2);
#pragma unroll
        for (int kk = 0; kk < 16; kk++) {
            const ulonglong2* ap = (const ulonglong2*)&Xs2[cur][kk][ty * 16];
            const ulonglong2* bp = (const ulonglong2*)&Ws[cur][kk][tx * 8];
            ulonglong2 a01 = ap[0], a23 = ap[1], a45 = ap[2], a67 = ap[3];
            ulonglong2 b03 = bp[0], b47 = bp[1];
            ull av[8] = {a01.x, a01.y, a23.x, a23.y, a45.x, a45.y, a67.x, a67.y};
            ull bv[4] = {b03.x, b03.y, b47.x, b47.y};
#pragma unroll
            for (int i = 0; i < 8; i++)
#pragma unroll
                for (int j = 0; j < 4; j++) fma2(acc[i][j], av[i], bv[j]);
        }
        if (kt + 1 < NK) ST(1 - cur, xf2, wf2);
        __syncthreads();
    }

#pragma unroll
    for (int i = 0; i < 8; i++) {
        int n = n0 + ty * 8 + i;
        float* crow = C + (size_t)n * E_;
        const float* rrow = res + (size_t)n * E_;
#pragma unroll
        for (int j = 0; j < 4; j++) {
            float lo, hi; unpack2(acc[i][j], lo, hi);
            int m = tx * 8 + 2 * j;
            crow[m]     = lo + rrow[m];
            crow[m + 1] = hi + rrow[m + 1];
        }
    }
}

// ---------------- depthwise causal conv (K=4) + silu; f/r paired on z -------
struct DWP { const float* cw; const float* cb; float* xc; int flip; };
__global__ void k_dwconv(const float* __restrict__ xz, DWP a, DWP b) {
    DWP p = blockIdx.z ? b : a;
    int idx = blockIdx.x * blockDim.x + threadIdx.x;
    if (idx >= (int)N_XC) return;
    int d = idx % DI;
    int bt = idx / DI;
    int t = bt % L_;
    int bb = bt / L_;
    float acc = p.cb[d];
#pragma unroll
    for (int j = 0; j < KC; j++) {
        int ti = t - 3 + j;
        if (ti >= 0 && ti < L_) {
            int ts = p.flip ? (L_ - 1 - ti) : ti;
            acc += p.cw[d * KC + j] * xz[((size_t)(bb * L_ + ts)) * (2 * DI) + d];
        }
    }
    p.xc[idx] = siluf(acc);
}

// ============================================================================
// selective scan: 8 threads per (b,d), 6 states each; delta fused in staging.
// ============================================================================
struct SCP { const float* xc; const float* xd; const float* dtw; const float* dtb;
             const float* Al; const float* Dp; float* y; };
#define SCT 32
__global__ void __launch_bounds__(256) k_scan(SCP pa, SCP pb) {
    SCP p = blockIdx.z ? pb : pa;
    __shared__ float sB[SCT][DS];
    __shared__ float sC[SCT][DS];
    __shared__ float sDel[SCT][32];
    __shared__ float sX[SCT][32];
    int b = blockIdx.y;
    int dbase = blockIdx.x * 32;
    int tid = threadIdx.x;
    int lane = tid & 31, w = tid >> 5;
    int grp = lane >> 3, sub = lane & 7;
    int d = dbase + w * 4 + grp;
    int di = w * 4 + grp;

    float A[6], h[6];
#pragma unroll
    for (int q = 0; q < 6; q++) {
        A[q] = -expf(p.Al[d * DS + sub * 6 + q]) * 1.4426950408889634f;
        h[q] = 0.0f;
    }
    float Dv = p.Dp[d];

    for (int t0 = 0; t0 < L_; t0 += SCT) {
        __syncthreads();
        for (int i = tid; i < SCT * 96; i += 256) {
            int r = i / 96, c = i - r * 96;
            float v = p.xd[(size_t)(b * L_ + t0 + r) * XD + DTR + c];
            if (c < DS) sB[r][c] = v; else sC[r][c - DS] = v;
        }
        for (int i = tid; i < SCT * 32; i += 256) {
            int r = i >> 5, c = i & 31;
            int dg = dbase + c;
            const float* row = p.xd + (size_t)(b * L_ + t0 + r) * XD;
            float acc = p.dtb[dg];
#pragma unroll
            for (int q = 0; q < DTR; q++) acc += row[q] * p.dtw[dg * DTR + q];
            sDel[r][c] = softplusf(acc);
            sX[r][c] = p.xc[(size_t)(b * L_ + t0 + r) * DI + dg];
        }
        __syncthreads();
#pragma unroll 4
        for (int tt = 0; tt < SCT; tt++) {
            float dv = sDel[tt][di], xv = sX[tt][di];
            float dx = dv * xv;
            const float2* Bp = (const float2*)&sB[tt][sub * 6];
            const float2* Cp = (const float2*)&sC[tt][sub * 6];
            float2 B0 = Bp[0], B1 = Bp[1], B2 = Bp[2];
            float2 C0 = Cp[0], C1 = Cp[1], C2 = Cp[2];
            float pr = 0.0f;
            h[0] = ex2f(dv * A[0]) * h[0] + dx * B0.x; pr = fmaf(h[0], C0.x, pr);
            h[1] = ex2f(dv * A[1]) * h[1] + dx * B0.y; pr = fmaf(h[1], C0.y, pr);
            h[2] = ex2f(dv * A[2]) * h[2] + dx * B1.x; pr = fmaf(h[2], C1.x, pr);
            h[3] = ex2f(dv * A[3]) * h[3] + dx * B1.y; pr = fmaf(h[3], C1.y, pr);
            h[4] = ex2f(dv * A[4]) * h[4] + dx * B2.x; pr = fmaf(h[4], C2.x, pr);
            h[5] = ex2f(dv * A[5]) * h[5] + dx * B2.y; pr = fmaf(h[5], C2.y, pr);
            pr += __shfl_xor_sync(0xffffffffu, pr, 1);
            pr += __shfl_xor_sync(0xffffffffu, pr, 2);
            pr += __shfl_xor_sync(0xffffffffu, pr, 4);
            if (sub == 0)
                p.y[(size_t)(b * L_ + t0 + tt) * DI + d] = pr + xv * Dv;
        }
    }
}

// ---------------- launcher --------------------------------------------------
extern "C" void kernel_launch(void* const* d_in, const int* in_sizes, int n_in,
                              void* d_out, int out_size) {
    const float* x     = (const float*)d_in[0];
    const float* cw0   = (const float*)d_in[1];
    const float* cb0   = (const float*)d_in[2];
    const float* convw = (const float*)d_in[3];
    const float* convb = (const float*)d_in[4];
    const float* pos   = (const float*)d_in[5];
    const float* lnw   = (const float*)d_in[6];
    const float* lnb   = (const float*)d_in[7];
    const float* ipw   = (const float*)d_in[8];
    const float* opw   = (const float*)d_in[9];
    const float* cw_f  = (const float*)d_in[10];
    const float* cb_f  = (const float*)d_in[11];
    const float* xp_f  = (const float*)d_in[12];
    const float* dtw_f = (const float*)d_in[13];
    const float* dtb_f = (const float*)d_in[14];
    const float* Al_f  = (const float*)d_in[15];
    const float* D_f   = (const float*)d_in[16];
    const float* cw_r  = (const float*)d_in[17];
    const float* cb_r  = (const float*)d_in[18];
    const float* xp_r  = (const float*)d_in[19];
    const float* dtw_r = (const float*)d_in[20];
    const float* dtb_r = (const float*)d_in[21];
    const float* Al_r  = (const float*)d_in[22];
    const float* D_r   = (const float*)d_in[23];
    float* out = (float*)d_out;

    float* S = nullptr;
    cudaGetSymbolAddress((void**)&S, g_scratch);
    float* gA  = S + OFF_GA;
    float* gB  = S + OFF_GB;
    float* ht  = S + OFF_HT;
    float* u   = S + OFF_U;
    float* xz  = S + OFF_XZ;
    float* xc0 = S + OFF_XC0;
    float* xc1 = S + OFF_XC1;
    float* xd0 = S + OFF_XD0;
    float* xd1 = S + OFF_XD1;
    float* y0  = S + OFF_Y0;
    float* y1  = S + OFF_Y1;

    const int TPB = 256;
    int gXC = (int)((N_XC + TPB - 1) / TPB);
    dim3 gdc(L_ / 128, 1, B_);

    // conv frontend: conv0 fused into dc0; gelu fused into producer epilogues;
    // residual+pos+transpose fused into dc3 epilogue.
    k_dilconv<1, 0><<<gdc, TPB>>>(nullptr, convw + 0 * 81920, convb + 0, gA, 2,
                                  x, cw0, cb0, nullptr);
    k_dilconv<0, 0><<<gdc, TPB>>>(gA, convw + 1 * 81920, convb + 128, gB, 4,
                                  nullptr, nullptr, nullptr, nullptr);
    k_dilconv<0, 0><<<gdc, TPB>>>(gB, convw + 2 * 81920, convb + 256, gA, 8,
                                  nullptr, nullptr, nullptr, nullptr);
    k_dilconv<0, 1><<<gdc, TPB>>>(gA, convw + 3 * 81920, convb + 384, ht, 16,
                                  x, nullptr, nullptr, pos);

    // BiMamba blocks
    for (int blk = 0; blk < 2; blk++) {
        k_ln<<<BL / 8, TPB>>>(ht, lnw + blk * E_, lnb + blk * E_, u);

        GP ip{u, ipw + (size_t)blk * 2 * DI * E_, nullptr, xz};
        k_gemm128<<<dim3(4, BL / 128, 1), TPB>>>(ip, ip, E_, E_, 2 * DI, 2 * DI);

        DWP dwa{cw_f + blk * DI * KC, cb_f + blk * DI, xc0, 0};
        DWP dwb{cw_r + blk * DI * KC, cb_r + blk * DI, xc1, 1};
        k_dwconv<<<dim3(gXC, 1, 2), TPB>>>(xz, dwa, dwb);

        GP xa{xc0, xp_f + (size_t)blk * XD * DI, nullptr, xd0};
        GP xb{xc1, xp_r + (size_t)blk * XD * DI, nullptr, xd1};
        k_gemm128<<<dim3(1, BL / 128, 2), TPB>>>(xa, xb, DI, DI, XD, XD);

        SCP sa{xc0, xd0, dtw_f + blk * DI * DTR, dtb_f + blk * DI,
               Al_f + (size_t)blk * DI * DS, D_f + blk * DI, y0};
        SCP sb{xc1, xd1, dtw_r + blk * DI * DTR, dtb_r + blk * DI,
               Al_r + (size_t)blk * DI * DS, D_r + blk * DI, y1};
        k_scan<<<dim3(DI / 32, B_, 2), TPB>>>(sa, sb);

        float* dst = (blk == 1) ? out : ht;
        k_gemm_out<<<dim3(1, BL / 128, 1), TPB>>>(
            y0, y1, xz, opw + (size_t)blk * E_ * DI, ht, dst);
    }
}